// round 7
// baseline (speedup 1.0000x reference)
#include <cuda_runtime.h>

#define N_TRAJ  256
#define T_LEN   1024
#define K_TYPES 1000
#define D_EMB   64
#define EPS     1e-8f

#define N_ROWS      (N_TRAJ * T_LEN)                   // 262144
#define EMB_TOTAL   (N_ROWS * D_EMB)                   // 16777216
#define EMB_BULK4   ((EMB_TOTAL - 4) / 4)              // 4194303 quads at pos 3+4q
#define QPT         4                                  // quads per thread
#define QUADS_PER_BLOCK (256 * QPT)                    // 1024 quads = 64 rows
#define EMB_BLOCKS  ((EMB_BULK4 + QUADS_PER_BLOCK - 1) / QUADS_PER_BLOCK)  // 4096

#define GATHER_BLOCKS 1024                             // 4 per trajectory

__device__ int   g_reduce_ctr;                 // zero-init; reset each launch
__device__ float g_part_ev[GATHER_BLOCKS];     // per-block partials (fixed slots)
__device__ float g_part_tm[GATHER_BLOCKS];

// ---------------------------------------------------------------------------
// Single fused kernel:
//   blocks [0, 1024)          : gather partials. Block g covers trajectory
//                               n = g/4, t-range (g%4)*256 + tid. One event
//                               per thread -> 1024 blocks' worth of warps
//                               issue the random DRAM loads chip-wide.
//                               Last-done block folds partials in FIXED order
//                               -> ll_N, time_loglik_NT, time_loglik.
//   blocks [1024, 1024+4096)  : embedding gather (QPT=4, smem indices,
//                               aligned overlapping LDG.128, __stcs stores).
// ---------------------------------------------------------------------------
__global__ void fused_kernel(const int* __restrict__ event_types,
                             const float* __restrict__ prob_event,
                             const float* __restrict__ intensities,
                             const float* __restrict__ Lambda,
                             const float* __restrict__ input_mask,
                             const float* __restrict__ type_table,
                             float* __restrict__ out,
                             float* __restrict__ out_emb) {
    const int tid = threadIdx.x;

    if (blockIdx.x < GATHER_BLOCKS) {
        // ---------------- gather partial path ----------------
        const int g   = blockIdx.x;
        const int n   = g >> 2;
        const int idx = n * T_LEN + (g & 3) * 256 + tid;

        const float m   = input_mask[idx];
        const float inz = intensities[idx];
        const int   e   = event_types[idx];
        const float p   = __ldcs(&prob_event[(long long)idx * K_TYPES + e]);

        const float tm = __logf(inz + EPS) * m;
        const float ev = __logf(p   + EPS) * m;

        __shared__ float s_ev[256];
        __shared__ float s_tm[256];
        s_ev[tid] = ev;
        s_tm[tid] = tm;
        __syncthreads();

        #pragma unroll
        for (int s = 128; s > 0; s >>= 1) {
            if (tid < s) {
                s_ev[tid] += s_ev[tid + s];
                s_tm[tid] += s_tm[tid + s];
            }
            __syncthreads();
        }

        if (tid == 0) {
            g_part_ev[g] = s_ev[0];
            g_part_tm[g] = s_tm[0];
        }

        // ----- deterministic fold in the last gather block -----
        __threadfence();                     // release partial writes
        __shared__ int is_last;
        if (tid == 0) {
            const int v = atomicAdd(&g_reduce_ctr, 1);
            is_last = (v == GATHER_BLOCKS - 1);
        }
        __syncthreads();
        if (is_last) {
            __threadfence();                 // acquire all partials
            // thread tid owns trajectory n = tid; fixed summation order
            float ev4 = 0.0f, tm4 = 0.0f;
            #pragma unroll
            for (int i = 0; i < 4; i++) {
                ev4 += g_part_ev[4 * tid + i];
                tm4 += g_part_tm[4 * tid + i];
            }
            const float tnt = tm4 - Lambda[tid];
            const float ll  = tnt + ev4;
            out[tid]              = ll;      // ll_N
            out[N_TRAJ + 1 + tid] = tnt;     // time_loglik_NT

            s_ev[tid] = ll;
            __syncthreads();
            #pragma unroll
            for (int s = 128; s > 0; s >>= 1) {
                if (tid < s) s_ev[tid] += s_ev[tid + s];
                __syncthreads();
            }
            if (tid == 0) {
                out[N_TRAJ] = s_ev[0];       // time_loglik (scalar)
                g_reduce_ctr = 0;            // reset for graph replay
            }
        }
        return;
    }

    // ---------------- embedding path ----------------
    const int b = blockIdx.x - GATHER_BLOCKS;          // 0 .. 4095

    // Stage the 65 event indices this block needs (rows 64b .. 64b+64).
    __shared__ int s_idx[65];
    if (tid < 65) {
        const int r = 64 * b + tid;
        s_idx[tid] = (r < N_ROWS) ? event_types[r] : 0;
    }
    __syncthreads();

    const int qbase = b * QUADS_PER_BLOCK + tid;

    int    pos[QPT];
    bool   ok[QPT];
    float4 lo[QPT], hi[QPT];

    // Phase 1: address math + issue all 8 independent LDG.128s.
    #pragma unroll
    for (int k = 0; k < QPT; k++) {
        const int q = qbase + k * 256;
        ok[k]  = (q < EMB_BULK4);                  // only very last quad fails
        pos[k] = 3 + 4 * q;
        const int lrow = (pos[k] >> 6) - 64 * b;   // 0..63
        const int d    = pos[k] & (D_EMB - 1);     // 3,7,...,63

        const int e  = s_idx[lrow];
        const int eb = (d == D_EMB - 1) ? s_idx[lrow + 1] : e;
        const int o  = (d == D_EMB - 1) ? 0 : d + 1;

        if (ok[k]) {
            lo[k] = __ldg((const float4*)(type_table + e  * D_EMB + (d - 3)));
            hi[k] = __ldg((const float4*)(type_table + eb * D_EMB + o));
        }
    }

    // Phase 2: recombine + streaming stores.
    #pragma unroll
    for (int k = 0; k < QPT; k++) {
        if (ok[k]) {
            float4 v;
            v.x = lo[k].w; v.y = hi[k].x; v.z = hi[k].y; v.w = hi[k].z;
            __stcs(reinterpret_cast<float4*>(out_emb + pos[k]), v);
        }
    }

    if (b == 0 && tid == 0) {
        // head pos 0,1,2 (row 0) and tail pos EMB_TOTAL-1
        const int eh = s_idx[0];
        out_emb[0] = __ldg(&type_table[eh * D_EMB + 0]);
        out_emb[1] = __ldg(&type_table[eh * D_EMB + 1]);
        out_emb[2] = __ldg(&type_table[eh * D_EMB + 2]);
        const int lrow = (EMB_TOTAL - 1) >> 6;
        const int el = __ldg(&event_types[lrow]);
        out_emb[EMB_TOTAL - 1] = __ldg(&type_table[el * D_EMB + (D_EMB - 1)]);
    }
}

extern "C" void kernel_launch(void* const* d_in, const int* in_sizes, int n_in,
                              void* d_out, int out_size) {
    const int*   event_types = (const int*)  d_in[0];   // (N, T) int32
    const float* prob_event  = (const float*)d_in[1];   // (N, T, K)
    const float* intensities = (const float*)d_in[2];   // (N, T)
    const float* Lambda      = (const float*)d_in[3];   // (N,)
    const float* input_mask  = (const float*)d_in[4];   // (N, T)
    const float* type_table  = (const float*)d_in[5];   // (K, D)

    float* out = (float*)d_out;
    // Layout: [ll_N (256)] [time_loglik (1)] [time_loglik_NT (256)] [type_emb]
    float* out_emb = out + (N_TRAJ + 1 + N_TRAJ);

    fused_kernel<<<GATHER_BLOCKS + EMB_BLOCKS, 256>>>(event_types, prob_event,
                                                      intensities, Lambda,
                                                      input_mask, type_table,
                                                      out, out_emb);
}